// round 3
// baseline (speedup 1.0000x reference)
#include <cuda_runtime.h>
#include <math.h>

#define Nn   8
#define Cc   64
#define Hh   128
#define Ww   128
#define HW   (Hh * Ww)          // 16384
#define TOT  (Nn * Cc * HW)     // 8388608
#define CCK  4                  // ci chunk staged in smem
#define TILE 16
#define COPT 16                 // output channels per thread
// 4 pixels per thread (2 f32x2 pairs)

__device__ float  g_y[TOT];
__device__ double g_sum[Cc];
__device__ double g_sq[Cc];
__device__ float  g_a[Cc];
__device__ float  g_b[Cc];

// ---------------------------------------------------------------------------
__global__ void k0_zero() {
    int t = threadIdx.x;
    if (t < Cc) { g_sum[t] = 0.0; g_sq[t] = 0.0; }
}

// ---- packed f32x2 helpers --------------------------------------------------
__device__ __forceinline__ unsigned long long pack2(float lo, float hi) {
    unsigned long long r;
    asm("mov.b64 %0, {%1, %2};"
        : "=l"(r) : "r"(__float_as_uint(lo)), "r"(__float_as_uint(hi)));
    return r;
}
__device__ __forceinline__ void unpack2(unsigned long long v, float& lo, float& hi) {
    unsigned int a, b;
    asm("mov.b64 {%0, %1}, %2;" : "=r"(a), "=r"(b) : "l"(v));
    lo = __uint_as_float(a); hi = __uint_as_float(b);
}
// acc += -| p + nw |   (nw holds {-w,-w}); 2x FADD2 (fma pipe) + 2x LOP3 (alu pipe)
__device__ __forceinline__ void accum(unsigned long long& acc,
                                      unsigned long long p,
                                      unsigned long long nw) {
    asm("{\n\t"
        ".reg .b64 d;\n\t"
        ".reg .b32 lo, hi;\n\t"
        "add.rn.f32x2 d, %1, %2;\n\t"
        "mov.b64 {lo, hi}, d;\n\t"
        "lop3.b32 lo, lo, 0x80000000, 0, 0xFC;\n\t"   // lo |= signbit -> -|lo|
        "lop3.b32 hi, hi, 0x80000000, 0, 0xFC;\n\t"
        "mov.b64 d, {lo, hi};\n\t"
        "add.rn.f32x2 %0, %0, d;\n\t"
        "}"
        : "+l"(acc) : "l"(p), "l"(nw));
}

// ---------------------------------------------------------------------------
// Pass 1: adder2d + residual -> g_y, per-channel sum/sumsq (double).
// CTA = 256 threads = 4 co-groups x 64 pixel-slots; pixel slot covers 4 cols.
// Tile 16x16 pixels; all weight LDS are warp-uniform broadcasts.
// ---------------------------------------------------------------------------
__global__ __launch_bounds__(256, 1)
void k1_adder(const float* __restrict__ x, const float* __restrict__ wgt) {
    __shared__ float xs[CCK][18][18];
    __shared__ __align__(16) unsigned long long ws[CCK][Cc][10]; // {-w,-w}, pad->16B
    __shared__ double ssum[Cc];
    __shared__ double ssq[Cc];

    const int n   = blockIdx.z;
    const int ty0 = blockIdx.y * TILE;
    const int tx0 = blockIdx.x * TILE;
    const int tid = threadIdx.x;
    const int g   = tid >> 6;          // co group (uniform within warp)
    const int p   = tid & 63;
    const int tr  = p >> 2;            // tile row 0..15
    const int tc4 = (p & 3) * 4;       // tile col base 0/4/8/12

    unsigned long long acc[COPT][2];
#pragma unroll
    for (int i = 0; i < COPT; i++) { acc[i][0] = 0ull; acc[i][1] = 0ull; }

    for (int cb = 0; cb < Cc; cb += CCK) {
        __syncthreads();
        // stage x halo tile
        for (int i = tid; i < CCK * 18 * 18; i += 256) {
            int ci = i / 324, r = (i / 18) % 18, c = i % 18;
            int gh = ty0 - 1 + r, gw = tx0 - 1 + c;
            float v = 0.0f;
            if ((unsigned)gh < 128u && (unsigned)gw < 128u)
                v = x[((n * Cc + cb + ci) * Hh + gh) * Ww + gw];
            xs[ci][r][c] = v;
        }
        // stage negated+duplicated weight pairs
        for (int i = tid; i < CCK * Cc * 9; i += 256) {
            int ci = i / (Cc * 9); int rem = i % (Cc * 9);
            int co = rem / 9, k = rem % 9;
            float v = -wgt[(co * Cc + cb + ci) * 9 + k];
            ws[ci][co][k] = pack2(v, v);
        }
        __syncthreads();

#pragma unroll
        for (int ci = 0; ci < CCK; ci++) {
            // pixel pairs for 3 rows: out cols tc4..tc4+3 need xs cols tc4..tc4+5
            unsigned long long A0[3], A1[3], A2[3], B0[3], B1[3];
#pragma unroll
            for (int kh = 0; kh < 3; kh++) {
                const float* row = &xs[ci][tr + kh][tc4];
                float x0 = row[0], x1 = row[1], x2 = row[2];
                float x3 = row[3], x4 = row[4], x5 = row[5];
                A0[kh] = pack2(x0, x1);
                B0[kh] = pack2(x1, x2);
                A1[kh] = pack2(x2, x3);
                B1[kh] = pack2(x3, x4);
                A2[kh] = pack2(x4, x5);
            }
#pragma unroll
            for (int c2 = 0; c2 < COPT; c2++) {
                const int co = g * COPT + c2;
                const ulonglong2* wp =
                    reinterpret_cast<const ulonglong2*>(&ws[ci][co][0]);
                ulonglong2 w01 = wp[0], w23 = wp[1], w45 = wp[2], w67 = wp[3];
                unsigned long long w8 = ws[ci][co][8];
                unsigned long long w[9] = {w01.x, w01.y, w23.x, w23.y,
                                           w45.x, w45.y, w67.x, w67.y, w8};
#pragma unroll
                for (int kh = 0; kh < 3; kh++) {
                    accum(acc[c2][0], A0[kh], w[kh * 3 + 0]);
                    accum(acc[c2][1], A1[kh], w[kh * 3 + 0]);
                    accum(acc[c2][0], B0[kh], w[kh * 3 + 1]);
                    accum(acc[c2][1], B1[kh], w[kh * 3 + 1]);
                    accum(acc[c2][0], A1[kh], w[kh * 3 + 2]);
                    accum(acc[c2][1], A2[kh], w[kh * 3 + 2]);
                }
            }
        }
    }

    // ---- epilogue: residual, y store, per-channel stats
    __syncthreads();
    if (tid < Cc) { ssum[tid] = 0.0; ssq[tid] = 0.0; }
    __syncthreads();

    const int h    = ty0 + tr;
    const int wc   = tx0 + tc4;
    const int lane = tid & 31;

#pragma unroll
    for (int c2 = 0; c2 < COPT; c2++) {
        const int co   = g * COPT + c2;
        const int base = ((n * Cc + co) * Hh + h) * Ww + wc;
        float4 xr = *reinterpret_cast<const float4*>(&x[base]);
        float y0, y1, y2, y3;
        unpack2(acc[c2][0], y0, y1);
        unpack2(acc[c2][1], y2, y3);
        y0 += xr.x; y1 += xr.y; y2 += xr.z; y3 += xr.w;
        float4 yo = make_float4(y0, y1, y2, y3);
        *reinterpret_cast<float4*>(&g_y[base]) = yo;

        float s = (y0 + y1) + (y2 + y3);
        float q = (y0 * y0 + y1 * y1) + (y2 * y2 + y3 * y3);
#pragma unroll
        for (int off = 16; off; off >>= 1) {
            s += __shfl_xor_sync(0xffffffffu, s, off);
            q += __shfl_xor_sync(0xffffffffu, q, off);
        }
        if (lane == 0) {
            atomicAdd(&ssum[co], (double)s);
            atomicAdd(&ssq[co], (double)q);
        }
    }
    __syncthreads();
    if (tid < Cc) {
        atomicAdd(&g_sum[tid], ssum[tid]);
        atomicAdd(&g_sq[tid],  ssq[tid]);
    }
}

// ---------------------------------------------------------------------------
__global__ void k2_stats(const float* __restrict__ gamma,
                         const float* __restrict__ beta) {
    int c = threadIdx.x;
    if (c < Cc) {
        const double cnt = (double)(Nn * HW);
        double mean = g_sum[c] / cnt;
        double var  = g_sq[c] / cnt - mean * mean;
        float inv   = (float)(1.0 / sqrt(var + 1e-5));
        float a     = gamma[c] * inv;
        g_a[c] = a;
        g_b[c] = beta[c] - (float)mean * a;
    }
}

// ---------------------------------------------------------------------------
__global__ void k3_out(float* __restrict__ out, const float* __restrict__ alpha) {
    const float al = *alpha;
    int i4 = blockIdx.x * blockDim.x + threadIdx.x;
    if (i4 < TOT / 4) {
        int i = i4 * 4;
        int c = (i >> 14) & 63;                       // HW = 2^14
        float a = g_a[c], b = g_b[c];
        float4 yv = *reinterpret_cast<const float4*>(&g_y[i]);
        float t0 = yv.x * a + b;
        float t1 = yv.y * a + b;
        float t2 = yv.z * a + b;
        float t3 = yv.w * a + b;
        float4 ov;
        if (al == 1.0f) {
            // sign(t)*(|t|+1e-12)^1 == t to within 1e-12 abs
            ov = make_float4(t0, t1, t2, t3);
        } else {
            float r0 = powf(fabsf(t0) + 1e-12f, al);
            float r1 = powf(fabsf(t1) + 1e-12f, al);
            float r2 = powf(fabsf(t2) + 1e-12f, al);
            float r3 = powf(fabsf(t3) + 1e-12f, al);
            ov.x = (t0 > 0.0f) ? r0 : ((t0 < 0.0f) ? -r0 : 0.0f);
            ov.y = (t1 > 0.0f) ? r1 : ((t1 < 0.0f) ? -r1 : 0.0f);
            ov.z = (t2 > 0.0f) ? r2 : ((t2 < 0.0f) ? -r2 : 0.0f);
            ov.w = (t3 > 0.0f) ? r3 : ((t3 < 0.0f) ? -r3 : 0.0f);
        }
        *reinterpret_cast<float4*>(&out[i]) = ov;
    }
}

// ---------------------------------------------------------------------------
extern "C" void kernel_launch(void* const* d_in, const int* in_sizes, int n_in,
                              void* d_out, int out_size) {
    const float* x     = (const float*)d_in[0];
    const float* wgt   = (const float*)d_in[1];
    const float* gamma = (const float*)d_in[2];
    const float* beta  = (const float*)d_in[3];
    const float* alpha = (const float*)d_in[4];
    float* out = (float*)d_out;

    k0_zero<<<1, 64>>>();
    dim3 grid(Ww / TILE, Hh / TILE, Nn);   // 8 x 8 x 8
    k1_adder<<<grid, 256>>>(x, wgt);
    k2_stats<<<1, 64>>>(gamma, beta);
    k3_out<<<(TOT / 4 + 255) / 256, 256>>>(out, alpha);
}

// round 4
// speedup vs baseline: 1.3367x; 1.3367x over previous
#include <cuda_runtime.h>
#include <math.h>

#define Nn   8
#define Cc   64
#define Hh   128
#define Ww   128
#define HW   (Hh * Ww)          // 16384
#define TOT  (Nn * Cc * HW)     // 8388608
#define CCK  8                  // ci chunk staged in smem
#define TILE 16
#define NCO2 32                 // co pairs

__device__ float  g_y[TOT];
__device__ double g_sum[Cc];
__device__ double g_sq[Cc];
__device__ float  g_a[Cc];
__device__ float  g_b[Cc];

// ---------------------------------------------------------------------------
__global__ void k0_zero() {
    int t = threadIdx.x;
    if (t < Cc) { g_sum[t] = 0.0; g_sq[t] = 0.0; }
}

// ---- packed f32x2 helpers --------------------------------------------------
__device__ __forceinline__ unsigned long long pack2(float lo, float hi) {
    unsigned long long r;
    asm("mov.b64 %0, {%1, %2};"
        : "=l"(r) : "r"(__float_as_uint(lo)), "r"(__float_as_uint(hi)));
    return r;
}
__device__ __forceinline__ void unpack2(unsigned long long v, float& lo, float& hi) {
    unsigned int a, b;
    asm("mov.b64 {%0, %1}, %2;" : "=r"(a), "=r"(b) : "l"(v));
    lo = __uint_as_float(a); hi = __uint_as_float(b);
}
// acc += -|p + nw|  (nw = {-w0,-w1}).  FADD2 ; OR.64(sign-force -> -|.|) ; FADD2
__device__ __forceinline__ void accum(unsigned long long& acc,
                                      unsigned long long p,
                                      unsigned long long nw) {
    asm("{\n\t"
        ".reg .b64 d;\n\t"
        "add.rn.f32x2 d, %1, %2;\n\t"
        "or.b64 d, d, 0x8000000080000000;\n\t"
        "add.rn.f32x2 %0, %0, d;\n\t"
        "}"
        : "+l"(acc) : "l"(p), "l"(nw));
}

// ---------------------------------------------------------------------------
// Pass 1: adder2d + residual -> g_y, per-channel sum/sumsq (double).
// 256 threads = 16x16 pixel tile, 1 pixel/thread, 32 packed co-pair accums.
// Weights staged in smem as {-w[2c], -w[2c+1]} pairs, k-contiguous, 96B stride.
// ---------------------------------------------------------------------------
__global__ __launch_bounds__(256, 2)
void k1_adder(const float* __restrict__ x, const float* __restrict__ wgt) {
    __shared__ float xs[CCK][18][18];
    __shared__ __align__(16) unsigned long long wt[CCK][NCO2][12]; // 9 used, pad 12
    __shared__ double ssum[Cc];
    __shared__ double ssq[Cc];

    const int n   = blockIdx.z;
    const int ty0 = blockIdx.y * TILE;
    const int tx0 = blockIdx.x * TILE;
    const int tid = threadIdx.x;
    const int tr  = tid >> 4;
    const int tc  = tid & 15;

    unsigned long long acc2[NCO2];
#pragma unroll
    for (int i = 0; i < NCO2; i++) acc2[i] = 0ull;

    for (int cb = 0; cb < Cc; cb += CCK) {
        __syncthreads();
        // stage x halo tile
        for (int i = tid; i < CCK * 18 * 18; i += 256) {
            int ci = i / 324, r = (i / 18) % 18, c = i % 18;
            int gh = ty0 - 1 + r, gw = tx0 - 1 + c;
            float v = 0.0f;
            if ((unsigned)gh < 128u && (unsigned)gw < 128u)
                v = x[((n * Cc + cb + ci) * Hh + gh) * Ww + gw];
            xs[ci][r][c] = v;
        }
        // stage weight pairs: wt[ci][co2][k] = { -w[2co2][cb+ci][k], -w[2co2+1][cb+ci][k] }
        for (int i = tid; i < CCK * NCO2 * 9; i += 256) {
            int ci  = i / (NCO2 * 9);
            int rem = i % (NCO2 * 9);
            int co2 = rem / 9, k = rem % 9;
            float v0 = -wgt[((2 * co2)     * Cc + cb + ci) * 9 + k];
            float v1 = -wgt[((2 * co2 + 1) * Cc + cb + ci) * 9 + k];
            wt[ci][co2][k] = pack2(v0, v1);
        }
        __syncthreads();

#pragma unroll 1
        for (int ci = 0; ci < CCK; ci++) {
            unsigned long long pp[9];
#pragma unroll
            for (int kh = 0; kh < 3; kh++)
#pragma unroll
                for (int kw = 0; kw < 3; kw++) {
                    float v = xs[ci][tr + kh][tc + kw];
                    pp[kh * 3 + kw] = pack2(v, v);
                }
#pragma unroll
            for (int co2 = 0; co2 < NCO2; co2++) {
                const ulonglong2* wp =
                    reinterpret_cast<const ulonglong2*>(&wt[ci][co2][0]);
                ulonglong2 w01 = wp[0], w23 = wp[1], w45 = wp[2], w67 = wp[3];
                unsigned long long w8 = wt[ci][co2][8];
                accum(acc2[co2], pp[0], w01.x);
                accum(acc2[co2], pp[1], w01.y);
                accum(acc2[co2], pp[2], w23.x);
                accum(acc2[co2], pp[3], w23.y);
                accum(acc2[co2], pp[4], w45.x);
                accum(acc2[co2], pp[5], w45.y);
                accum(acc2[co2], pp[6], w67.x);
                accum(acc2[co2], pp[7], w67.y);
                accum(acc2[co2], pp[8], w8);
            }
        }
    }

    // ---- epilogue: residual, y store, per-channel stats
    __syncthreads();
    if (tid < Cc) { ssum[tid] = 0.0; ssq[tid] = 0.0; }
    __syncthreads();

    const int h    = ty0 + tr;
    const int w    = tx0 + tc;
    const int lane = tid & 31;
    const int pixb = n * Cc * HW + h * Ww + w;

#pragma unroll
    for (int co2 = 0; co2 < NCO2; co2++) {
        const int c0 = 2 * co2;
        float y0, y1;
        unpack2(acc2[co2], y0, y1);
        y0 += x[pixb + c0 * HW];
        y1 += x[pixb + (c0 + 1) * HW];
        g_y[pixb + c0 * HW]       = y0;
        g_y[pixb + (c0 + 1) * HW] = y1;

        float s0 = y0, q0 = y0 * y0;
        float s1 = y1, q1 = y1 * y1;
#pragma unroll
        for (int off = 16; off; off >>= 1) {
            s0 += __shfl_xor_sync(0xffffffffu, s0, off);
            q0 += __shfl_xor_sync(0xffffffffu, q0, off);
            s1 += __shfl_xor_sync(0xffffffffu, s1, off);
            q1 += __shfl_xor_sync(0xffffffffu, q1, off);
        }
        if (lane == 0) {
            atomicAdd(&ssum[c0],     (double)s0);
            atomicAdd(&ssq[c0],      (double)q0);
            atomicAdd(&ssum[c0 + 1], (double)s1);
            atomicAdd(&ssq[c0 + 1],  (double)q1);
        }
    }
    __syncthreads();
    if (tid < Cc) {
        atomicAdd(&g_sum[tid], ssum[tid]);
        atomicAdd(&g_sq[tid],  ssq[tid]);
    }
}

// ---------------------------------------------------------------------------
__global__ void k2_stats(const float* __restrict__ gamma,
                         const float* __restrict__ beta) {
    int c = threadIdx.x;
    if (c < Cc) {
        const double cnt = (double)(Nn * HW);
        double mean = g_sum[c] / cnt;
        double var  = g_sq[c] / cnt - mean * mean;
        float inv   = (float)(1.0 / sqrt(var + 1e-5));
        float a     = gamma[c] * inv;
        g_a[c] = a;
        g_b[c] = beta[c] - (float)mean * a;
    }
}

// ---------------------------------------------------------------------------
__global__ void k3_out(float* __restrict__ out, const float* __restrict__ alpha) {
    const float al = *alpha;
    int i4 = blockIdx.x * blockDim.x + threadIdx.x;
    if (i4 < TOT / 4) {
        int i = i4 * 4;
        int c = (i >> 14) & 63;                       // HW = 2^14
        float a = g_a[c], b = g_b[c];
        float4 yv = *reinterpret_cast<const float4*>(&g_y[i]);
        float t0 = yv.x * a + b;
        float t1 = yv.y * a + b;
        float t2 = yv.z * a + b;
        float t3 = yv.w * a + b;
        float4 ov;
        if (al == 1.0f) {
            ov = make_float4(t0, t1, t2, t3);   // sign(t)*(|t|+1e-12) == t to 1e-12
        } else {
            float r0 = powf(fabsf(t0) + 1e-12f, al);
            float r1 = powf(fabsf(t1) + 1e-12f, al);
            float r2 = powf(fabsf(t2) + 1e-12f, al);
            float r3 = powf(fabsf(t3) + 1e-12f, al);
            ov.x = (t0 > 0.0f) ? r0 : ((t0 < 0.0f) ? -r0 : 0.0f);
            ov.y = (t1 > 0.0f) ? r1 : ((t1 < 0.0f) ? -r1 : 0.0f);
            ov.z = (t2 > 0.0f) ? r2 : ((t2 < 0.0f) ? -r2 : 0.0f);
            ov.w = (t3 > 0.0f) ? r3 : ((t3 < 0.0f) ? -r3 : 0.0f);
        }
        *reinterpret_cast<float4*>(&out[i]) = ov;
    }
}

// ---------------------------------------------------------------------------
extern "C" void kernel_launch(void* const* d_in, const int* in_sizes, int n_in,
                              void* d_out, int out_size) {
    const float* x     = (const float*)d_in[0];
    const float* wgt   = (const float*)d_in[1];
    const float* gamma = (const float*)d_in[2];
    const float* beta  = (const float*)d_in[3];
    const float* alpha = (const float*)d_in[4];
    float* out = (float*)d_out;

    k0_zero<<<1, 64>>>();
    dim3 grid(Ww / TILE, Hh / TILE, Nn);   // 8 x 8 x 8
    k1_adder<<<grid, 256>>>(x, wgt);
    k2_stats<<<1, 64>>>(gamma, beta);
    k3_out<<<(TOT / 4 + 255) / 256, 256>>>(out, alpha);
}

// round 7
// speedup vs baseline: 1.3555x; 1.0141x over previous
#include <cuda_runtime.h>
#include <math.h>

#define Nn   8
#define Cc   64
#define Hh   128
#define Ww   128
#define HW   (Hh * Ww)          // 16384
#define TOT  (Nn * Cc * HW)     // 8388608
#define CCK  8                  // ci chunk staged in smem
#define TILE 16
#define NCO2 32                 // co pairs

__device__ float  g_y[TOT];
__device__ double g_sum[Cc];
__device__ double g_sq[Cc];
__device__ float  g_a[Cc];
__device__ float  g_b[Cc];

// ---------------------------------------------------------------------------
__global__ void k0_zero() {
    int t = threadIdx.x;
    if (t < Cc) { g_sum[t] = 0.0; g_sq[t] = 0.0; }
}

// ---- packed f32x2 helpers --------------------------------------------------
__device__ __forceinline__ unsigned long long pack2(float lo, float hi) {
    unsigned long long r;
    asm("mov.b64 %0, {%1, %2};"
        : "=l"(r) : "r"(__float_as_uint(lo)), "r"(__float_as_uint(hi)));
    return r;
}
__device__ __forceinline__ void unpack2(unsigned long long v, float& lo, float& hi) {
    unsigned int a, b;
    asm("mov.b64 {%0, %1}, %2;" : "=r"(a), "=r"(b) : "l"(v));
    lo = __uint_as_float(a); hi = __uint_as_float(b);
}
// acc += -|p + nw|  (nw = {-w0,-w1}).
// FFMA2(p,1,nw) ; OR.64 sign-force -> -|.| ; FFMA2(d,1,acc)
// fma.rn.f32x2 is the ONLY PTX form ptxas maps to real FFMA2 (2x fp32 rate).
__device__ __forceinline__ void accum(unsigned long long& acc,
                                      unsigned long long p,
                                      unsigned long long nw,
                                      unsigned long long one2) {
    asm("{\n\t"
        ".reg .b64 d;\n\t"
        "fma.rn.f32x2 d, %1, %3, %2;\n\t"
        "or.b64 d, d, 0x8000000080000000;\n\t"
        "fma.rn.f32x2 %0, d, %3, %0;\n\t"
        "}"
        : "+l"(acc) : "l"(p), "l"(nw), "l"(one2));
}

// ---------------------------------------------------------------------------
// Pass 1: adder2d + residual -> g_y, per-channel sum/sumsq (double).
// 256 threads = 16x16 pixel tile, 1 pixel/thread, 32 packed co-pair accums.
// Weights staged in smem as {-w[2c], -w[2c+1]} pairs, k-contiguous, 96B stride.
// ---------------------------------------------------------------------------
__global__ __launch_bounds__(256, 2)
void k1_adder(const float* __restrict__ x, const float* __restrict__ wgt) {
    __shared__ float xs[CCK][18][18];
    __shared__ __align__(16) unsigned long long wt[CCK][NCO2][12]; // 9 used, pad 12
    __shared__ double ssum[Cc];
    __shared__ double ssq[Cc];

    const int n   = blockIdx.z;
    const int ty0 = blockIdx.y * TILE;
    const int tx0 = blockIdx.x * TILE;
    const int tid = threadIdx.x;
    const int tr  = tid >> 4;
    const int tc  = tid & 15;

    const unsigned long long one2 = 0x3F8000003F800000ull;  // {1.0f, 1.0f}

    unsigned long long acc2[NCO2];
#pragma unroll
    for (int i = 0; i < NCO2; i++) acc2[i] = 0ull;

    for (int cb = 0; cb < Cc; cb += CCK) {
        __syncthreads();
        // stage x halo tile
        for (int i = tid; i < CCK * 18 * 18; i += 256) {
            int ci = i / 324, r = (i / 18) % 18, c = i % 18;
            int gh = ty0 - 1 + r, gw = tx0 - 1 + c;
            float v = 0.0f;
            if ((unsigned)gh < 128u && (unsigned)gw < 128u)
                v = x[((n * Cc + cb + ci) * Hh + gh) * Ww + gw];
            xs[ci][r][c] = v;
        }
        // stage weight pairs: wt[ci][co2][k] = { -w[2co2][cb+ci][k], -w[2co2+1][cb+ci][k] }
        for (int i = tid; i < CCK * NCO2 * 9; i += 256) {
            int ci  = i / (NCO2 * 9);
            int rem = i % (NCO2 * 9);
            int co2 = rem / 9, k = rem % 9;
            float v0 = -wgt[((2 * co2)     * Cc + cb + ci) * 9 + k];
            float v1 = -wgt[((2 * co2 + 1) * Cc + cb + ci) * 9 + k];
            wt[ci][co2][k] = pack2(v0, v1);
        }
        __syncthreads();

#pragma unroll 1
        for (int ci = 0; ci < CCK; ci++) {
            unsigned long long pp[9];
#pragma unroll
            for (int kh = 0; kh < 3; kh++)
#pragma unroll
                for (int kw = 0; kw < 3; kw++) {
                    float v = xs[ci][tr + kh][tc + kw];
                    pp[kh * 3 + kw] = pack2(v, v);
                }
#pragma unroll
            for (int co2 = 0; co2 < NCO2; co2++) {
                const ulonglong2* wp =
                    reinterpret_cast<const ulonglong2*>(&wt[ci][co2][0]);
                ulonglong2 w01 = wp[0], w23 = wp[1], w45 = wp[2], w67 = wp[3];
                unsigned long long w8 = wt[ci][co2][8];
                accum(acc2[co2], pp[0], w01.x, one2);
                accum(acc2[co2], pp[1], w01.y, one2);
                accum(acc2[co2], pp[2], w23.x, one2);
                accum(acc2[co2], pp[3], w23.y, one2);
                accum(acc2[co2], pp[4], w45.x, one2);
                accum(acc2[co2], pp[5], w45.y, one2);
                accum(acc2[co2], pp[6], w67.x, one2);
                accum(acc2[co2], pp[7], w67.y, one2);
                accum(acc2[co2], pp[8], w8,    one2);
            }
        }
    }

    // ---- epilogue: residual, y store, per-channel stats
    __syncthreads();
    if (tid < Cc) { ssum[tid] = 0.0; ssq[tid] = 0.0; }
    __syncthreads();

    const int h    = ty0 + tr;
    const int w    = tx0 + tc;
    const int lane = tid & 31;
    const int pixb = n * Cc * HW + h * Ww + w;

#pragma unroll
    for (int co2 = 0; co2 < NCO2; co2++) {
        const int c0 = 2 * co2;
        float y0, y1;
        unpack2(acc2[co2], y0, y1);
        y0 += x[pixb + c0 * HW];
        y1 += x[pixb + (c0 + 1) * HW];
        g_y[pixb + c0 * HW]       = y0;
        g_y[pixb + (c0 + 1) * HW] = y1;

        float s0 = y0, q0 = y0 * y0;
        float s1 = y1, q1 = y1 * y1;
#pragma unroll
        for (int off = 16; off; off >>= 1) {
            s0 += __shfl_xor_sync(0xffffffffu, s0, off);
            q0 += __shfl_xor_sync(0xffffffffu, q0, off);
            s1 += __shfl_xor_sync(0xffffffffu, s1, off);
            q1 += __shfl_xor_sync(0xffffffffu, q1, off);
        }
        if (lane == 0) {
            atomicAdd(&ssum[c0],     (double)s0);
            atomicAdd(&ssq[c0],      (double)q0);
            atomicAdd(&ssum[c0 + 1], (double)s1);
            atomicAdd(&ssq[c0 + 1],  (double)q1);
        }
    }
    __syncthreads();
    if (tid < Cc) {
        atomicAdd(&g_sum[tid], ssum[tid]);
        atomicAdd(&g_sq[tid],  ssq[tid]);
    }
}

// ---------------------------------------------------------------------------
__global__ void k2_stats(const float* __restrict__ gamma,
                         const float* __restrict__ beta) {
    int c = threadIdx.x;
    if (c < Cc) {
        const double cnt = (double)(Nn * HW);
        double mean = g_sum[c] / cnt;
        double var  = g_sq[c] / cnt - mean * mean;
        float inv   = (float)(1.0 / sqrt(var + 1e-5));
        float a     = gamma[c] * inv;
        g_a[c] = a;
        g_b[c] = beta[c] - (float)mean * a;
    }
}

// ---------------------------------------------------------------------------
__global__ void k3_out(float* __restrict__ out, const float* __restrict__ alpha) {
    const float al = *alpha;
    int i4 = blockIdx.x * blockDim.x + threadIdx.x;
    if (i4 < TOT / 4) {
        int i = i4 * 4;
        int c = (i >> 14) & 63;                       // HW = 2^14
        float a = g_a[c], b = g_b[c];
        float4 yv = *reinterpret_cast<const float4*>(&g_y[i]);
        float t0 = yv.x * a + b;
        float t1 = yv.y * a + b;
        float t2 = yv.z * a + b;
        float t3 = yv.w * a + b;
        float4 ov;
        if (al == 1.0f) {
            ov = make_float4(t0, t1, t2, t3);   // sign(t)*(|t|+1e-12) == t to 1e-12
        } else {
            float r0 = powf(fabsf(t0) + 1e-12f, al);
            float r1 = powf(fabsf(t1) + 1e-12f, al);
            float r2 = powf(fabsf(t2) + 1e-12f, al);
            float r3 = powf(fabsf(t3) + 1e-12f, al);
            ov.x = (t0 > 0.0f) ? r0 : ((t0 < 0.0f) ? -r0 : 0.0f);
            ov.y = (t1 > 0.0f) ? r1 : ((t1 < 0.0f) ? -r1 : 0.0f);
            ov.z = (t2 > 0.0f) ? r2 : ((t2 < 0.0f) ? -r2 : 0.0f);
            ov.w = (t3 > 0.0f) ? r3 : ((t3 < 0.0f) ? -r3 : 0.0f);
        }
        *reinterpret_cast<float4*>(&out[i]) = ov;
    }
}

// ---------------------------------------------------------------------------
extern "C" void kernel_launch(void* const* d_in, const int* in_sizes, int n_in,
                              void* d_out, int out_size) {
    const float* x     = (const float*)d_in[0];
    const float* wgt   = (const float*)d_in[1];
    const float* gamma = (const float*)d_in[2];
    const float* beta  = (const float*)d_in[3];
    const float* alpha = (const float*)d_in[4];
    float* out = (float*)d_out;

    k0_zero<<<1, 64>>>();
    dim3 grid(Ww / TILE, Hh / TILE, Nn);   // 8 x 8 x 8
    k1_adder<<<grid, 256>>>(x, wgt);
    k2_stats<<<1, 64>>>(gamma, beta);
    k3_out<<<(TOT / 4 + 255) / 256, 256>>>(out, alpha);
}